// round 2
// baseline (speedup 1.0000x reference)
#include <cuda_runtime.h>

// SNN: B=1024 batch, T=4096 steps, layers 6 -> 10 -> 27 (LIF, subtract-reset).
// One warp per batch element. Layer-2 current is looked up from a 1024-entry
// SMEM table indexed by the 10-bit spike mask produced by __ballot_sync.
// Membrane update uses FFMA (beta*mem + cur) to match XLA's contracted codegen.

#define T_LEN 4096
#define NB 1024
#define BETA 0.9f
#define WARPS_PER_CTA 8
#define CTA_THREADS (WARPS_PER_CTA * 32)
#define N_CTAS (NB / WARPS_PER_CTA) /* 128 */

#define TABLE_FLOATS (1024 * 27 + 32)      /* +32 pad so lanes 27..31 stay in-bounds */
#define CURBUF_STRIDE 33                   /* conflict-free staging */
#define CURBUF_FLOATS (32 * CURBUF_STRIDE) /* 1056 per warp */
#define SMEM_FLOATS (TABLE_FLOATS + WARPS_PER_CTA * CURBUF_FLOATS)
#define SMEM_BYTES (SMEM_FLOATS * 4)       /* 144,512 B */

__global__ void __launch_bounds__(CTA_THREADS, 1)
snn_kernel(const float* __restrict__ x, const float* __restrict__ W1,
           const float* __restrict__ b1, const float* __restrict__ W2,
           const float* __restrict__ b2, float* __restrict__ out)
{
    extern __shared__ float smem[];
    float* table  = smem;                 // [1024][27] (+pad)
    float* curall = smem + TABLE_FLOATS;  // [WARPS][32][33]

    const int tid = threadIdx.x;

    // ---- Layer-2 lookup: table[v*27+m] = sum_{n set in v} W2[m][n] + b2[m].
    // Ascending-n accumulation == reference fma-dot with 0/1 spikes (adding 0 is exact).
    for (int e = tid; e < 1024 * 27; e += CTA_THREADS) {
        int v = e / 27;
        int m = e - v * 27;
        float acc = 0.0f;
#pragma unroll
        for (int n = 0; n < 10; n++)
            if (v & (1 << n)) acc = __fadd_rn(acc, W2[m * 10 + n]);
        table[e] = __fadd_rn(acc, b2[m]);
    }
    for (int i = tid; i < WARPS_PER_CTA * CURBUF_FLOATS; i += CTA_THREADS)
        curall[i] = 0.0f;
    for (int i = 1024 * 27 + tid; i < TABLE_FLOATS; i += CTA_THREADS)
        table[i] = 0.0f;
    __syncthreads();

    const int warp = tid >> 5;
    const int lane = tid & 31;
    const int b = blockIdx.x * WARPS_PER_CTA + warp;
    float* cbuf = curall + warp * CURBUF_FLOATS;

    float w1r[10][6], b1r[10];
#pragma unroll
    for (int n = 0; n < 10; n++) {
        b1r[n] = b1[n];
#pragma unroll
        for (int c = 0; c < 6; c++) w1r[n][c] = W1[n * 6 + c];
    }

    const float* xb = x + (size_t)b * (6 * T_LEN);
    const float* trow = table + lane;

    float m1 = 0.0f, m2 = 0.0f, s1 = 0.0f, s2 = 0.0f;
    const bool is_l1 = (lane < 10);

    for (int t0 = 0; t0 < T_LEN; t0 += 32) {
        __syncwarp();

        // ---- Phase A: lane j computes cur1[0..9] for timestep t0+j.
        // Ascending-k FFMA chain from 0 == cublas SGEMM accumulation order.
        float xv[6];
#pragma unroll
        for (int c = 0; c < 6; c++)
            xv[c] = xb[c * T_LEN + t0 + lane];

#pragma unroll
        for (int n = 0; n < 10; n++) {
            float a = __fmul_rn(xv[0], w1r[n][0]);  // == fma(x0,w0,0)
#pragma unroll
            for (int c = 1; c < 6; c++)
                a = fmaf(xv[c], w1r[n][c], a);
            cbuf[lane * CURBUF_STRIDE + n] = __fadd_rn(a, b1r[n]);
        }
        __syncwarp();

        // ---- Phase B: 32 serial recurrence steps
#pragma unroll
        for (int j = 0; j < 32; j++) {
            float c1 = cbuf[j * CURBUF_STRIDE + lane];
            // FFMA contraction (matches XLA AllowFPOpFusion=Fast); -s exact.
            m1 = __fsub_rn(fmaf(BETA, m1, c1), s1);
            unsigned msk = __ballot_sync(0xffffffffu, is_l1 && (m1 > 1.0f));
            s1 = (m1 > 1.0f) ? 1.0f : 0.0f;

            float c2 = trow[msk * 27u];
            m2 = __fsub_rn(fmaf(BETA, m2, c2), s2);
            s2 = (m2 > 1.0f) ? 1.0f : 0.0f;
        }
    }

    if (lane < 27)
        out[b * 27 + lane] = s2;
}

extern "C" void kernel_launch(void* const* d_in, const int* in_sizes, int n_in,
                              void* d_out, int out_size)
{
    const float* x  = (const float*)d_in[0];
    const float* W1 = (const float*)d_in[1];
    const float* b1 = (const float*)d_in[2];
    const float* W2 = (const float*)d_in[3];
    const float* b2 = (const float*)d_in[4];
    float* out = (float*)d_out;

    cudaFuncSetAttribute(snn_kernel, cudaFuncAttributeMaxDynamicSharedMemorySize,
                         SMEM_BYTES);

    snn_kernel<<<N_CTAS, CTA_THREADS, SMEM_BYTES>>>(x, W1, b1, W2, b2, out);
}

// round 3
// speedup vs baseline: 1.0107x; 1.0107x over previous
#include <cuda_runtime.h>

// SNN: B=1024, T=4096, 6 -> 10 -> 27 LIF (subtract reset). One warp per batch
// element. Layer-2 current via 1024x27 SMEM lookup indexed by ballot of layer-1
// spikes. Double-buffered cur1 staging + 2-chunk x prefetch; spike state kept
// as predicate; membrane update in select form (bit-exact with reference).

#define T_LEN 4096
#define NB 1024
#define BETA 0.9f
#define WARPS_PER_CTA 8
#define CTA_THREADS (WARPS_PER_CTA * 32)
#define N_CTAS (NB / WARPS_PER_CTA) /* 128 */
#define NCHUNK (T_LEN / 32)         /* 128 */

#define TABLE_FLOATS (1024 * 27 + 32)      /* +pad so lanes 27..31 stay in-bounds */
#define CURBUF_STRIDE 33                   /* conflict-free staging */
#define CURBUF_FLOATS (32 * CURBUF_STRIDE) /* 1056 per bank */
#define CURBUF_PER_WARP (2 * CURBUF_FLOATS)
#define SMEM_FLOATS (TABLE_FLOATS + WARPS_PER_CTA * CURBUF_PER_WARP)
#define SMEM_BYTES (SMEM_FLOATS * 4)       /* 178,304 B */

__device__ __forceinline__ void phaseA_store(const float xv[6],
                                             const float w1r[10][6],
                                             const float b1r[10],
                                             float* wb, int lane)
{
    // Ascending-k FFMA chain from 0 == cublas accumulation order; then +b1.
#pragma unroll
    for (int n = 0; n < 10; n++) {
        float a = __fmul_rn(xv[0], w1r[n][0]);
#pragma unroll
        for (int c = 1; c < 6; c++)
            a = fmaf(xv[c], w1r[n][c], a);
        wb[lane * CURBUF_STRIDE + n] = __fadd_rn(a, b1r[n]);
    }
}

__global__ void __launch_bounds__(CTA_THREADS, 1)
snn_kernel(const float* __restrict__ x, const float* __restrict__ W1,
           const float* __restrict__ b1, const float* __restrict__ W2,
           const float* __restrict__ b2, float* __restrict__ out)
{
    extern __shared__ float smem[];
    float* table  = smem;                 // [1024][27] (+pad)
    float* curall = smem + TABLE_FLOATS;  // [WARPS][2][32][33]

    const int tid  = threadIdx.x;
    const int warp = tid >> 5;
    const int lane = tid & 31;
    const int b = blockIdx.x * WARPS_PER_CTA + warp;
    const float* xb = x + (size_t)b * (6 * T_LEN);

    // Kick off chunk-0 x loads before the table build so LDG overlaps it.
    float xcur[6];
#pragma unroll
    for (int c = 0; c < 6; c++) xcur[c] = xb[c * T_LEN + lane];

    // ---- Layer-2 lookup: table[v*27+m] = sum_{n set in v} W2[m][n] + b2[m].
    // Ascending-n accumulation == reference fma-dot with 0/1 spikes.
    for (int e = tid; e < 1024 * 27; e += CTA_THREADS) {
        int v = e / 27;
        int m = e - v * 27;
        float acc = 0.0f;
#pragma unroll
        for (int n = 0; n < 10; n++)
            if (v & (1 << n)) acc = __fadd_rn(acc, W2[m * 10 + n]);
        table[e] = __fadd_rn(acc, b2[m]);
    }
    for (int i = 1024 * 27 + tid; i < TABLE_FLOATS; i += CTA_THREADS)
        table[i] = 0.0f;
    // zero staging (columns 10..31 stay zero forever -> lanes 10..31 never spike)
    for (int i = tid; i < WARPS_PER_CTA * CURBUF_PER_WARP; i += CTA_THREADS)
        curall[i] = 0.0f;
    __syncthreads();

    float w1r[10][6], b1r[10];
#pragma unroll
    for (int n = 0; n < 10; n++) {
        b1r[n] = b1[n];
#pragma unroll
        for (int c = 0; c < 6; c++) w1r[n][c] = W1[n * 6 + c];
    }

    float* cbuf = curall + warp * CURBUF_PER_WARP;
    const float* trow = table + lane;

    // Prologue: phase A chunk 0 -> bank 0; prefetch chunk 1.
    phaseA_store(xcur, w1r, b1r, cbuf, lane);
    float xv[6];
#pragma unroll
    for (int c = 0; c < 6; c++) xv[c] = xb[c * T_LEN + 32 + lane];
    __syncwarp();

    float m1 = 0.0f, m2 = 0.0f;
    bool p1 = false, p2 = false;

    for (int k = 0; k < NCHUNK; k++) {
        float* rb = cbuf + (k & 1) * CURBUF_FLOATS;
        float* wb = cbuf + ((k + 1) & 1) * CURBUF_FLOATS;

        // Prefetch chunk k+2 (lands during this chunk's phase B).
        float xnext[6];
        if (k + 2 < NCHUNK) {
#pragma unroll
            for (int c = 0; c < 6; c++)
                xnext[c] = xb[c * T_LEN + (k + 2) * 32 + lane];
        }
        // Phase A for chunk k+1 into the other bank — independent of phase B,
        // fills its latency stalls.
        if (k + 1 < NCHUNK)
            phaseA_store(xv, w1r, b1r, wb, lane);

        // ---- Phase B: 32 serial recurrence steps on bank rb
#pragma unroll
        for (int j = 0; j < 32; j++) {
            float c1 = rb[j * CURBUF_STRIDE + lane];
            // reference: mem = fma(beta,mem,cur) - rst ; rst in {0,1}.
            // select form is bit-exact (x-0 == x; fsub(x,1) identical op).
            float a1 = fmaf(BETA, m1, c1);
            float d1 = __fsub_rn(a1, 1.0f);
            m1 = p1 ? d1 : a1;
            p1 = (m1 > 1.0f);
            unsigned msk = __ballot_sync(0xffffffffu, p1); // bits 10..31 always 0

            float c2 = trow[msk * 27u];
            float a2 = fmaf(BETA, m2, c2);
            float d2 = __fsub_rn(a2, 1.0f);
            m2 = p2 ? d2 : a2;
            p2 = (m2 > 1.0f);
        }

        if (k + 2 < NCHUNK) {
#pragma unroll
            for (int c = 0; c < 6; c++) xv[c] = xnext[c];
        }
        __syncwarp();  // wb writes visible before next chunk reads them
    }

    if (lane < 27)
        out[b * 27 + lane] = p2 ? 1.0f : 0.0f;
}

extern "C" void kernel_launch(void* const* d_in, const int* in_sizes, int n_in,
                              void* d_out, int out_size)
{
    const float* x  = (const float*)d_in[0];
    const float* W1 = (const float*)d_in[1];
    const float* b1 = (const float*)d_in[2];
    const float* W2 = (const float*)d_in[3];
    const float* b2 = (const float*)d_in[4];
    float* out = (float*)d_out;

    cudaFuncSetAttribute(snn_kernel, cudaFuncAttributeMaxDynamicSharedMemorySize,
                         SMEM_BYTES);

    snn_kernel<<<N_CTAS, CTA_THREADS, SMEM_BYTES>>>(x, W1, b1, W2, b2, out);
}

// round 4
// speedup vs baseline: 1.1363x; 1.1242x over previous
#include <cuda_runtime.h>

// SNN: B=1024, T=4096, 6 -> 10 -> 27 LIF (subtract reset). One warp per batch
// element. Layer-2 current via 1024x27 SMEM table indexed by ballot of layer-1
// spikes. KEY STRUCTURE: layer-2 runs one chunk (32 steps) behind layer-1, with
// its currents prefetched into a register array during layer-1's chunk, so the
// slow FSETP->VOTE->LDS path is off the critical chain. Two independent ~17cyc
// recurrence chains per warp, interleaved by the scheduler.

#define T_LEN 4096
#define NB 1024
#define BETA 0.9f
#define WARPS_PER_CTA 8
#define CTA_THREADS (WARPS_PER_CTA * 32)
#define N_CTAS (NB / WARPS_PER_CTA) /* 128 */
#define NCHUNK (T_LEN / 32)         /* 128 */

#define TABLE_FLOATS (1024 * 27 + 32)
#define CURBUF_STRIDE 33
#define CURBUF_FLOATS (32 * CURBUF_STRIDE)
#define CURBUF_PER_WARP (2 * CURBUF_FLOATS)
#define SMEM_FLOATS (TABLE_FLOATS + WARPS_PER_CTA * CURBUF_PER_WARP)
#define SMEM_BYTES (SMEM_FLOATS * 4) /* 178,304 B */

__device__ __forceinline__ void phaseA_store(const float xv[6],
                                             const float w1r[10][6],
                                             const float b1r[10],
                                             float* wb, int lane)
{
    // Ascending-k FFMA chain from 0 == cublas accumulation order; then +b1.
#pragma unroll
    for (int n = 0; n < 10; n++) {
        float a = __fmul_rn(xv[0], w1r[n][0]);
#pragma unroll
        for (int c = 1; c < 6; c++)
            a = fmaf(xv[c], w1r[n][c], a);
        wb[lane * CURBUF_STRIDE + n] = __fadd_rn(a, b1r[n]);
    }
}

// One fused chunk: layer-1 recurrence over rb (32 steps) producing c2new[],
// layer-2 recurrence consuming c2old[] (chunk-delayed). Both chains independent.
template <bool DO_L2>
__device__ __forceinline__ void fused_chunk(const float* rb, int lane,
                                            const float* trow,
                                            float& m1, bool& p1,
                                            float& m2, bool& p2,
                                            float (&c2new)[32],
                                            const float (&c2old)[32])
{
#pragma unroll
    for (int j = 0; j < 32; j++) {
        // ---- layer 1 (chunk k): mem = fma(beta,mem,cur) - rst  (bit-exact
        // select form: subtracting 0 is exact; fsub(a,1) is the same op).
        float c1 = rb[j * CURBUF_STRIDE + lane];
        float a1 = fmaf(BETA, m1, c1);
        float d1 = __fsub_rn(a1, 1.0f);
        m1 = p1 ? d1 : a1;
        p1 = (m1 > 1.0f);
        unsigned msk = __ballot_sync(0xffffffffu, p1); // bits 10..31 always 0
        c2new[j] = trow[msk * 27u];  // off-chain: consumed 32 steps later

        // ---- layer 2 (chunk k-1): pure register chain
        if (DO_L2) {
            float a2 = fmaf(BETA, m2, c2old[j]);
            float d2 = __fsub_rn(a2, 1.0f);
            m2 = p2 ? d2 : a2;
            p2 = (m2 > 1.0f);
        }
    }
}

__global__ void __launch_bounds__(CTA_THREADS, 1)
snn_kernel(const float* __restrict__ x, const float* __restrict__ W1,
           const float* __restrict__ b1, const float* __restrict__ W2,
           const float* __restrict__ b2, float* __restrict__ out)
{
    extern __shared__ float smem[];
    float* table  = smem;                 // [1024][27] (+pad)
    float* curall = smem + TABLE_FLOATS;  // [WARPS][2][32][33]

    const int tid  = threadIdx.x;
    const int warp = tid >> 5;
    const int lane = tid & 31;
    const int b = blockIdx.x * WARPS_PER_CTA + warp;
    const float* xb = x + (size_t)b * (6 * T_LEN);

    // chunk-0 x loads overlap the table build
    float xv[6];
#pragma unroll
    for (int c = 0; c < 6; c++) xv[c] = xb[c * T_LEN + lane];

    // Layer-2 lookup table: ascending-n accumulation == reference fma-dot
    // with 0/1 spikes (adding 0.0f is exact).
    for (int e = tid; e < 1024 * 27; e += CTA_THREADS) {
        int v = e / 27;
        int m = e - v * 27;
        float acc = 0.0f;
#pragma unroll
        for (int n = 0; n < 10; n++)
            if (v & (1 << n)) acc = __fadd_rn(acc, W2[m * 10 + n]);
        table[e] = __fadd_rn(acc, b2[m]);
    }
    for (int i = 1024 * 27 + tid; i < TABLE_FLOATS; i += CTA_THREADS)
        table[i] = 0.0f;
    // staging columns 10..31 stay zero forever -> lanes 10..31 never spike
    for (int i = tid; i < WARPS_PER_CTA * CURBUF_PER_WARP; i += CTA_THREADS)
        curall[i] = 0.0f;
    __syncthreads();

    float w1r[10][6], b1r[10];
#pragma unroll
    for (int n = 0; n < 10; n++) {
        b1r[n] = b1[n];
#pragma unroll
        for (int c = 0; c < 6; c++) w1r[n][c] = W1[n * 6 + c];
    }

    float* cbuf = curall + warp * CURBUF_PER_WARP;
    float* bank0 = cbuf;
    float* bank1 = cbuf + CURBUF_FLOATS;
    const float* trow = table + lane;

    float m1 = 0.0f, m2 = 0.0f;
    bool p1 = false, p2 = false;
    float c2a[32], c2b[32];
#pragma unroll
    for (int j = 0; j < 32; j++) { c2a[j] = 0.0f; c2b[j] = 0.0f; }

    // Prologue: phaseA(ch0)->bank0, load x for ch1.
    phaseA_store(xv, w1r, b1r, bank0, lane);
#pragma unroll
    for (int c = 0; c < 6; c++) xv[c] = xb[c * T_LEN + 32 + lane];
    __syncwarp();

    // Chunk 0: L1 only -> c2a ; phaseA(ch1)->bank1 ; prefetch x ch2.
    {
        float xn[6];
#pragma unroll
        for (int c = 0; c < 6; c++) xn[c] = xb[c * T_LEN + 64 + lane];
        phaseA_store(xv, w1r, b1r, bank1, lane);
        fused_chunk<false>(bank0, lane, trow, m1, p1, m2, p2, c2a, c2b);
#pragma unroll
        for (int c = 0; c < 6; c++) xv[c] = xn[c];
        __syncwarp();
    }

    // Main: chunks 1..126 in pairs. Chunk k: L1(k) from bank(k&1), L2(k-1);
    // phaseA(k+1) into the other bank; x prefetch k+2.
#pragma unroll 1
    for (int k = 1; k <= 125; k += 2) {
        // --- chunk k (odd): rb=bank1, wb=bank0, L1->c2b, L2 consumes c2a
        {
            float xn[6];
#pragma unroll
            for (int c = 0; c < 6; c++)
                xn[c] = xb[c * T_LEN + (k + 2) * 32 + lane];
            phaseA_store(xv, w1r, b1r, bank0, lane);
            fused_chunk<true>(bank1, lane, trow, m1, p1, m2, p2, c2b, c2a);
#pragma unroll
            for (int c = 0; c < 6; c++) xv[c] = xn[c];
            __syncwarp();
        }
        // --- chunk k+1 (even): rb=bank0, wb=bank1, L1->c2a, L2 consumes c2b
        {
            float xn[6];
#pragma unroll
            for (int c = 0; c < 6; c++)
                xn[c] = xb[c * T_LEN + (k + 3) * 32 + lane];
            phaseA_store(xv, w1r, b1r, bank1, lane);
            fused_chunk<true>(bank0, lane, trow, m1, p1, m2, p2, c2a, c2b);
#pragma unroll
            for (int c = 0; c < 6; c++) xv[c] = xn[c];
            __syncwarp();
        }
    }

    // Chunk 127 (odd): L1(127) from bank1 -> c2b, L2(126) consumes c2a.
    fused_chunk<true>(bank1, lane, trow, m1, p1, m2, p2, c2b, c2a);

    // Epilogue: L2(127) consumes c2b.
#pragma unroll
    for (int j = 0; j < 32; j++) {
        float a2 = fmaf(BETA, m2, c2b[j]);
        float d2 = __fsub_rn(a2, 1.0f);
        m2 = p2 ? d2 : a2;
        p2 = (m2 > 1.0f);
    }

    if (lane < 27)
        out[b * 27 + lane] = p2 ? 1.0f : 0.0f;
}

extern "C" void kernel_launch(void* const* d_in, const int* in_sizes, int n_in,
                              void* d_out, int out_size)
{
    const float* x  = (const float*)d_in[0];
    const float* W1 = (const float*)d_in[1];
    const float* b1 = (const float*)d_in[2];
    const float* W2 = (const float*)d_in[3];
    const float* b2 = (const float*)d_in[4];
    float* out = (float*)d_out;

    cudaFuncSetAttribute(snn_kernel, cudaFuncAttributeMaxDynamicSharedMemorySize,
                         SMEM_BYTES);

    snn_kernel<<<N_CTAS, CTA_THREADS, SMEM_BYTES>>>(x, W1, b1, W2, b2, out);
}

// round 5
// speedup vs baseline: 1.3160x; 1.1581x over previous
#include <cuda_runtime.h>

// SNN: B=1024, T=4096, 6 -> 10 -> 27 LIF (subtract reset). One warp per batch.
// Layer-2 current via 1024x27 SMEM table indexed by ballot of layer-1 spikes,
// consumed one chunk (32 steps) later from a register array.
// R5: c1 loads batched into registers ahead of the votes (LDS never downstream
// of VOTE on the chain), float-subtrahend spike state, f32x2-packed phase A.

#define T_LEN 4096
#define NB 1024
#define BETA 0.9f
#define WARPS_PER_CTA 8
#define CTA_THREADS (WARPS_PER_CTA * 32)
#define N_CTAS (NB / WARPS_PER_CTA) /* 128 */
#define NCHUNK (T_LEN / 32)         /* 128 */

#define TABLE_FLOATS (1024 * 27 + 32)
#define CURBUF_STRIDE 34                   /* even: aligned 64-bit stores; reads conflict-free */
#define CURBUF_FLOATS (32 * CURBUF_STRIDE) /* 1088 */
#define CURBUF_PER_WARP (2 * CURBUF_FLOATS)
#define SMEM_FLOATS (TABLE_FLOATS + WARPS_PER_CTA * CURBUF_PER_WARP)
#define SMEM_BYTES (SMEM_FLOATS * 4) /* 180,352 B */

typedef unsigned long long u64;

__device__ __forceinline__ u64 pack2(float lo, float hi) {
    u64 r; asm("mov.b64 %0,{%1,%2};" : "=l"(r) : "f"(lo), "f"(hi)); return r;
}
__device__ __forceinline__ u64 mul2(u64 a, u64 b) {
    u64 r; asm("mul.rn.f32x2 %0,%1,%2;" : "=l"(r) : "l"(a), "l"(b)); return r;
}
__device__ __forceinline__ u64 fma2(u64 a, u64 b, u64 c) {
    u64 r; asm("fma.rn.f32x2 %0,%1,%2,%3;" : "=l"(r) : "l"(a), "l"(b), "l"(c)); return r;
}
__device__ __forceinline__ u64 add2(u64 a, u64 b) {
    u64 r; asm("add.rn.f32x2 %0,%1,%2;" : "=l"(r) : "l"(a), "l"(b)); return r;
}

// Phase A: 10 neuron currents for this lane's timestep, packed in f32x2 pairs.
// Per-half rounding of mul/fma/add.rn.f32x2 == scalar __fmul_rn/fmaf/__fadd_rn,
// so accumulation order (ascending k, then +b1) still matches cublas exactly.
__device__ __forceinline__ void phaseA_store(const float xv[6],
                                             const u64 w12r[5][6],
                                             const u64 b12r[5],
                                             float* wb, int lane)
{
    u64 xx[6];
#pragma unroll
    for (int c = 0; c < 6; c++) xx[c] = pack2(xv[c], xv[c]);
#pragma unroll
    for (int np = 0; np < 5; np++) {
        u64 a = mul2(xx[0], w12r[np][0]);
#pragma unroll
        for (int c = 1; c < 6; c++)
            a = fma2(xx[c], w12r[np][c], a);
        a = add2(a, b12r[np]);
        *reinterpret_cast<u64*>(&wb[lane * CURBUF_STRIDE + 2 * np]) = a; // aligned
    }
}

// One chunk: layer-1 recurrence (32 steps) producing c2new[] via ballot+table,
// layer-2 recurrence consuming c2old[] (chunk-delayed, register-resident).
// c1 values batch-loaded 8 ahead so no LDS is ordered after a VOTE on the chain.
template <bool DO_L2>
__device__ __forceinline__ void fused_chunk(const float* rb, int lane,
                                            const float* trow,
                                            float& m1, float& s1,
                                            float& m2, float& s2,
                                            float (&c2new)[32],
                                            const float (&c2old)[32])
{
#pragma unroll
    for (int jj = 0; jj < 32; jj += 8) {
        float c1r[8];
#pragma unroll
        for (int i = 0; i < 8; i++)
            c1r[i] = rb[(jj + i) * CURBUF_STRIDE + lane];
#pragma unroll
        for (int i = 0; i < 8; i++) {
            // reference: mem = fma(beta,mem,cur) - rst; rst in {0,1} exact.
            float a1 = fmaf(BETA, m1, c1r[i]);
            m1 = __fsub_rn(a1, s1);
            s1 = (m1 > 1.0f) ? 1.0f : 0.0f;
            unsigned msk = __ballot_sync(0xffffffffu, m1 > 1.0f); // bits 10..31 always 0
            c2new[jj + i] = trow[msk * 27u];  // sink: consumed next chunk

            if (DO_L2) {
                float a2 = fmaf(BETA, m2, c2old[jj + i]);
                m2 = __fsub_rn(a2, s2);
                s2 = (m2 > 1.0f) ? 1.0f : 0.0f;
            }
        }
    }
}

__global__ void __launch_bounds__(CTA_THREADS, 1)
snn_kernel(const float* __restrict__ x, const float* __restrict__ W1,
           const float* __restrict__ b1, const float* __restrict__ W2,
           const float* __restrict__ b2, float* __restrict__ out)
{
    extern __shared__ float smem[];
    float* table  = smem;                 // [1024][27] (+pad)
    float* curall = smem + TABLE_FLOATS;  // [WARPS][2][32][34]

    const int tid  = threadIdx.x;
    const int warp = tid >> 5;
    const int lane = tid & 31;
    const int b = blockIdx.x * WARPS_PER_CTA + warp;
    const float* xb = x + (size_t)b * (6 * T_LEN);

    // chunk-0 x loads overlap the table build
    float xv[6];
#pragma unroll
    for (int c = 0; c < 6; c++) xv[c] = xb[c * T_LEN + lane];

    // Layer-2 lookup table: ascending-n accumulation == reference fma-dot
    // with 0/1 spikes (adding 0.0f is exact).
    for (int e = tid; e < 1024 * 27; e += CTA_THREADS) {
        int v = e / 27;
        int m = e - v * 27;
        float acc = 0.0f;
#pragma unroll
        for (int n = 0; n < 10; n++)
            if (v & (1 << n)) acc = __fadd_rn(acc, W2[m * 10 + n]);
        table[e] = __fadd_rn(acc, b2[m]);
    }
    for (int i = 1024 * 27 + tid; i < TABLE_FLOATS; i += CTA_THREADS)
        table[i] = 0.0f;
    // staging columns 10..31 stay zero forever -> lanes 10..31 never spike
    for (int i = tid; i < WARPS_PER_CTA * CURBUF_PER_WARP; i += CTA_THREADS)
        curall[i] = 0.0f;
    __syncthreads();

    // W1/b1 packed into f32x2 neuron pairs
    u64 w12r[5][6], b12r[5];
#pragma unroll
    for (int np = 0; np < 5; np++) {
        b12r[np] = pack2(b1[2 * np], b1[2 * np + 1]);
#pragma unroll
        for (int c = 0; c < 6; c++)
            w12r[np][c] = pack2(W1[(2 * np) * 6 + c], W1[(2 * np + 1) * 6 + c]);
    }

    float* cbuf  = curall + warp * CURBUF_PER_WARP;
    float* bank0 = cbuf;
    float* bank1 = cbuf + CURBUF_FLOATS;
    const float* trow = table + lane;

    float m1 = 0.0f, m2 = 0.0f, s1 = 0.0f, s2 = 0.0f;
    float c2a[32], c2b[32];
#pragma unroll
    for (int j = 0; j < 32; j++) { c2a[j] = 0.0f; c2b[j] = 0.0f; }

    // Prologue: phaseA(ch0)->bank0, load x for ch1.
    phaseA_store(xv, w12r, b12r, bank0, lane);
#pragma unroll
    for (int c = 0; c < 6; c++) xv[c] = xb[c * T_LEN + 32 + lane];
    __syncwarp();

    // Chunk 0: L1 only -> c2a ; phaseA(ch1)->bank1 ; prefetch x ch2.
    phaseA_store(xv, w12r, b12r, bank1, lane);
#pragma unroll
    for (int c = 0; c < 6; c++) xv[c] = xb[c * T_LEN + 64 + lane];
    fused_chunk<false>(bank0, lane, trow, m1, s1, m2, s2, c2a, c2b);
    __syncwarp();

    // Main: chunks 1..126 in pairs.
#pragma unroll 1
    for (int k = 1; k <= 125; k += 2) {
        // chunk k (odd): rb=bank1, wb=bank0, L1->c2b, L2 consumes c2a
        phaseA_store(xv, w12r, b12r, bank0, lane);
#pragma unroll
        for (int c = 0; c < 6; c++) xv[c] = xb[c * T_LEN + (k + 2) * 32 + lane];
        fused_chunk<true>(bank1, lane, trow, m1, s1, m2, s2, c2b, c2a);
        __syncwarp();

        // chunk k+1 (even): rb=bank0, wb=bank1, L1->c2a, L2 consumes c2b
        phaseA_store(xv, w12r, b12r, bank1, lane);
        if (k + 3 < NCHUNK) {
#pragma unroll
            for (int c = 0; c < 6; c++) xv[c] = xb[c * T_LEN + (k + 3) * 32 + lane];
        }
        fused_chunk<true>(bank0, lane, trow, m1, s1, m2, s2, c2a, c2b);
        __syncwarp();
    }

    // Chunk 127 (odd): L1(127) from bank1 -> c2b, L2(126) consumes c2a.
    fused_chunk<true>(bank1, lane, trow, m1, s1, m2, s2, c2b, c2a);

    // Epilogue: L2(127) consumes c2b.
#pragma unroll
    for (int j = 0; j < 32; j++) {
        float a2 = fmaf(BETA, m2, c2b[j]);
        m2 = __fsub_rn(a2, s2);
        s2 = (m2 > 1.0f) ? 1.0f : 0.0f;
    }

    if (lane < 27)
        out[b * 27 + lane] = s2;

    (void)NCHUNK;
}

extern "C" void kernel_launch(void* const* d_in, const int* in_sizes, int n_in,
                              void* d_out, int out_size)
{
    const float* x  = (const float*)d_in[0];
    const float* W1 = (const float*)d_in[1];
    const float* b1 = (const float*)d_in[2];
    const float* W2 = (const float*)d_in[3];
    const float* b2 = (const float*)d_in[4];
    float* out = (float*)d_out;

    cudaFuncSetAttribute(snn_kernel, cudaFuncAttributeMaxDynamicSharedMemorySize,
                         SMEM_BYTES);

    snn_kernel<<<N_CTAS, CTA_THREADS, SMEM_BYTES>>>(x, W1, b1, W2, b2, out);
}

// round 6
// speedup vs baseline: 1.4459x; 1.0988x over previous
#include <cuda_runtime.h>

// SNN: B=1024, T=4096, 6 -> 10 -> 27 LIF (subtract reset). One warp per batch.
// Three-stage register pipeline (8-step sub-batches):
//   sub s   : layer-1 recurrence -> ballot masks (VOTE results unconsumed)
//   sub s+1 : table fetch c2 = table[msk*27]     (masks >=8 steps old)
//   sub s+2 : layer-2 recurrence consumes c2     (LDS >=8 steps old)
// => no scoreboard waits inside the serial region; VOTE/LDS are pure sinks.

#define T_LEN 4096
#define NB 1024
#define BETA 0.9f
#define WARPS_PER_CTA 8
#define CTA_THREADS (WARPS_PER_CTA * 32)
#define N_CTAS (NB / WARPS_PER_CTA) /* 128 */
#define NCHUNK (T_LEN / 32)         /* 128 */

#define ZERO_ROW 1024u                     /* table row of zeros (pad region) */
#define TABLE_FLOATS (1024 * 27 + 32)
#define CURBUF_STRIDE 34                   /* even: aligned 64-bit stores */
#define CURBUF_FLOATS (32 * CURBUF_STRIDE)
#define CURBUF_PER_WARP (2 * CURBUF_FLOATS)
#define SMEM_FLOATS (TABLE_FLOATS + WARPS_PER_CTA * CURBUF_PER_WARP)
#define SMEM_BYTES (SMEM_FLOATS * 4) /* 180,352 B */

typedef unsigned long long u64;

__device__ __forceinline__ u64 pack2(float lo, float hi) {
    u64 r; asm("mov.b64 %0,{%1,%2};" : "=l"(r) : "f"(lo), "f"(hi)); return r;
}
__device__ __forceinline__ u64 mul2(u64 a, u64 b) {
    u64 r; asm("mul.rn.f32x2 %0,%1,%2;" : "=l"(r) : "l"(a), "l"(b)); return r;
}
__device__ __forceinline__ u64 fma2(u64 a, u64 b, u64 c) {
    u64 r; asm("fma.rn.f32x2 %0,%1,%2,%3;" : "=l"(r) : "l"(a), "l"(b), "l"(c)); return r;
}
__device__ __forceinline__ u64 add2(u64 a, u64 b) {
    u64 r; asm("add.rn.f32x2 %0,%1,%2;" : "=l"(r) : "l"(a), "l"(b)); return r;
}

// Phase A: 10 neuron currents for this lane's timestep, f32x2-packed.
// Per-half rounding == scalar ops; ascending-k order matches cublas.
__device__ __forceinline__ void phaseA_store(const float xv[6],
                                             const u64 w12r[5][6],
                                             const u64 b12r[5],
                                             float* wb, int lane)
{
    u64 xx[6];
#pragma unroll
    for (int c = 0; c < 6; c++) xx[c] = pack2(xv[c], xv[c]);
#pragma unroll
    for (int np = 0; np < 5; np++) {
        u64 a = mul2(xx[0], w12r[np][0]);
#pragma unroll
        for (int c = 1; c < 6; c++)
            a = fma2(xx[c], w12r[np][c], a);
        a = add2(a, b12r[np]);
        *reinterpret_cast<u64*>(&wb[lane * CURBUF_STRIDE + 2 * np]) = a;
    }
}

// One chunk = 4 sub-batches of 8 steps. Parity p alternates 0,1,0,1 each chunk
// (4 subs/chunk -> chunk-invariant), carrying the 3-stage pipeline state.
__device__ __forceinline__ void fused_chunk(const float* rb, int lane,
                                            const float* trow,
                                            float& m1, float& s1,
                                            float& m2, float& s2,
                                            unsigned (&msk)[2][8],
                                            float (&c2f)[2][8])
{
#pragma unroll
    for (int sb = 0; sb < 4; sb++) {
        const int p = sb & 1, q = p ^ 1;
        float c1r[8];
#pragma unroll
        for (int i = 0; i < 8; i++)
            c1r[i] = rb[(sb * 8 + i) * CURBUF_STRIDE + lane];
        // fetch c2 for the previous sub-batch's masks (VOTE long drained);
        // results consumed only next sub-batch (LDS long drained).
#pragma unroll
        for (int i = 0; i < 8; i++)
            c2f[p][i] = trow[msk[q][i] * 27u];
#pragma unroll
        for (int i = 0; i < 8; i++) {
            // reference: mem = fma(beta,mem,cur) - rst ; rst in {0,1} exact.
            float a1 = fmaf(BETA, m1, c1r[i]);
            m1 = __fsub_rn(a1, s1);
            bool sp = (m1 > 1.0f);
            s1 = sp ? 1.0f : 0.0f;
            msk[p][i] = __ballot_sync(0xffffffffu, sp); // sink (bits 10..31 = 0)

            float a2 = fmaf(BETA, m2, c2f[q][i]);
            m2 = __fsub_rn(a2, s2);
            s2 = (m2 > 1.0f) ? 1.0f : 0.0f;
        }
    }
}

__global__ void __launch_bounds__(CTA_THREADS, 1)
snn_kernel(const float* __restrict__ x, const float* __restrict__ W1,
           const float* __restrict__ b1, const float* __restrict__ W2,
           const float* __restrict__ b2, float* __restrict__ out)
{
    extern __shared__ float smem[];
    float* table  = smem;                 // [1024][27] + 32 zero pad (ZERO_ROW)
    float* curall = smem + TABLE_FLOATS;  // [WARPS][2][32][34]

    const int tid  = threadIdx.x;
    const int warp = tid >> 5;
    const int lane = tid & 31;
    const int b = blockIdx.x * WARPS_PER_CTA + warp;
    const float* xb = x + (size_t)b * (6 * T_LEN);

    float xv[6];
#pragma unroll
    for (int c = 0; c < 6; c++) xv[c] = xb[c * T_LEN + lane];

    // Layer-2 lookup table: ascending-n accumulation == reference fma-dot
    // with 0/1 spikes (adding 0.0f is exact).
    for (int e = tid; e < 1024 * 27; e += CTA_THREADS) {
        int v = e / 27;
        int m = e - v * 27;
        float acc = 0.0f;
#pragma unroll
        for (int n = 0; n < 10; n++)
            if (v & (1 << n)) acc = __fadd_rn(acc, W2[m * 10 + n]);
        table[e] = __fadd_rn(acc, b2[m]);
    }
    for (int i = 1024 * 27 + tid; i < TABLE_FLOATS; i += CTA_THREADS)
        table[i] = 0.0f;  // ZERO_ROW lives here
    // staging columns 10..31 stay zero forever -> lanes 10..31 never spike
    for (int i = tid; i < WARPS_PER_CTA * CURBUF_PER_WARP; i += CTA_THREADS)
        curall[i] = 0.0f;
    __syncthreads();

    u64 w12r[5][6], b12r[5];
#pragma unroll
    for (int np = 0; np < 5; np++) {
        b12r[np] = pack2(b1[2 * np], b1[2 * np + 1]);
#pragma unroll
        for (int c = 0; c < 6; c++)
            w12r[np][c] = pack2(W1[(2 * np) * 6 + c], W1[(2 * np + 1) * 6 + c]);
    }

    float* cbuf  = curall + warp * CURBUF_PER_WARP;
    float* bank0 = cbuf;
    float* bank1 = cbuf + CURBUF_FLOATS;
    const float* trow = table + lane;

    float m1 = 0.0f, m2 = 0.0f, s1 = 0.0f, s2 = 0.0f;
    unsigned msk[2][8];
    float c2f[2][8];
#pragma unroll
    for (int i = 0; i < 8; i++) {
        msk[0][i] = ZERO_ROW; msk[1][i] = ZERO_ROW; // -> zero pad row
        c2f[0][i] = 0.0f;     c2f[1][i] = 0.0f;     // fake steps keep m2 == 0
    }

    // Prologue: phaseA(ch0)->bank0; xv <- ch1.
    phaseA_store(xv, w12r, b12r, bank0, lane);
#pragma unroll
    for (int c = 0; c < 6; c++) xv[c] = xb[c * T_LEN + 32 + lane];
    __syncwarp();

    // Chunks 0..125 in pairs.
#pragma unroll 1
    for (int k = 0; k < 126; k += 2) {
        // even chunk k: read bank0; phaseA(k+1)->bank1; prefetch x(k+2)
        float xn[6];
#pragma unroll
        for (int c = 0; c < 6; c++)
            xn[c] = xb[c * T_LEN + (k + 2) * 32 + lane];
        phaseA_store(xv, w12r, b12r, bank1, lane);
        fused_chunk(bank0, lane, trow, m1, s1, m2, s2, msk, c2f);
#pragma unroll
        for (int c = 0; c < 6; c++) xv[c] = xn[c];
        __syncwarp();

        // odd chunk k+1: read bank1; phaseA(k+2)->bank0; prefetch x(k+3)
#pragma unroll
        for (int c = 0; c < 6; c++)
            xn[c] = xb[c * T_LEN + (k + 3) * 32 + lane];
        phaseA_store(xv, w12r, b12r, bank0, lane);
        fused_chunk(bank1, lane, trow, m1, s1, m2, s2, msk, c2f);
#pragma unroll
        for (int c = 0; c < 6; c++) xv[c] = xn[c];
        __syncwarp();
    }

    // chunk 126: read bank0; phaseA(127)->bank1
    phaseA_store(xv, w12r, b12r, bank1, lane);
    fused_chunk(bank0, lane, trow, m1, s1, m2, s2, msk, c2f);
    __syncwarp();
    // chunk 127: read bank1
    fused_chunk(bank1, lane, trow, m1, s1, m2, s2, msk, c2f);

    // Epilogue: L2 lags by 16 steps. Last sub-batch had parity 1:
    // consume c2f[1] (sub 510's currents), then fetch+consume sub 511's.
#pragma unroll
    for (int i = 0; i < 8; i++) {
        float a2 = fmaf(BETA, m2, c2f[1][i]);
        m2 = __fsub_rn(a2, s2);
        s2 = (m2 > 1.0f) ? 1.0f : 0.0f;
    }
#pragma unroll
    for (int i = 0; i < 8; i++) {
        float c = trow[msk[1][i] * 27u];
        float a2 = fmaf(BETA, m2, c);
        m2 = __fsub_rn(a2, s2);
        s2 = (m2 > 1.0f) ? 1.0f : 0.0f;
    }

    if (lane < 27)
        out[b * 27 + lane] = s2;
}

extern "C" void kernel_launch(void* const* d_in, const int* in_sizes, int n_in,
                              void* d_out, int out_size)
{
    const float* x  = (const float*)d_in[0];
    const float* W1 = (const float*)d_in[1];
    const float* b1 = (const float*)d_in[2];
    const float* W2 = (const float*)d_in[3];
    const float* b2 = (const float*)d_in[4];
    float* out = (float*)d_out;

    cudaFuncSetAttribute(snn_kernel, cudaFuncAttributeMaxDynamicSharedMemorySize,
                         SMEM_BYTES);

    snn_kernel<<<N_CTAS, CTA_THREADS, SMEM_BYTES>>>(x, W1, b1, W2, b2, out);
}